// round 16
// baseline (speedup 1.0000x reference)
#include <cuda_runtime.h>

#define N_SLOTS 524288
#define DIM     128
#define NF      138        // DIM_MEM + 1 + 1 + 7 + 1
#define DIN     1024
#define TPB     256
#define NWARPS  8
#define MB      304                // 2 CTAs per SM on 152 SMs (all resident)
#define FB      160                // factor-stage blocks
#define KCH     32                 // k chunks of 32 rows
#define NWT     (MB * NWARPS)      // 2432 warps
#define NG      (N_SLOTS / 4)      // 131072 groups of 4 rows

// scratch (allocation-free: __device__ globals)
__device__ __align__(16) float g_fpart[KCH][160];
__device__ float g_UpartT[DIM][MB];
__device__ float g_Zpart[MB];
__device__ int   g_cnt1 = 0;
__device__ int   g_cnt2 = 0;

#define FULLM 0xffffffffu

__device__ __forceinline__ float fullred(float v) {
    #pragma unroll
    for (int o = 16; o; o >>= 1) v += __shfl_xor_sync(FULLM, v, o);
    return v;
}

// steady-state: contiguous rows, streaming hint, no wrap arithmetic
__device__ __forceinline__ void loadgrp_fast(float4 (&buf)[4], const float* __restrict__ mem,
                                             int rowbase, int lane) {
    const float4* p = (const float4*)(mem + (size_t)rowbase * DIM) + lane;
    #pragma unroll
    for (int i = 0; i < 4; i++) buf[i] = __ldcs(p + i * 32);
}

__device__ __forceinline__ void loadgrp_wrap(float4 (&buf)[4], const float* __restrict__ mem,
                                             int rowbase, int lane) {
    #pragma unroll
    for (int i = 0; i < 4; i++) {
        int r = rowbase + i;
        r += (r < 0) ? N_SLOTS : 0;
        r -= (r >= N_SLOTS) ? N_SLOTS : 0;
        buf[i] = ((const float4*)(mem + (size_t)r * DIM))[lane];
    }
}

// butterfly: 4 rows -> e values written to warp-private ring (slots (lr+3)&15)
__device__ __forceinline__ void bfly_e(const float4 (&m)[4], const float4 kv,
                                       float ks, float stab, float ikn,
                                       float* ring, int lr0, int lane, int minrow) {
    float d[4], q[4];
    #pragma unroll
    for (int u = 0; u < 4; u++) {
        d[u] = m[u].x*kv.x + m[u].y*kv.y + m[u].z*kv.z + m[u].w*kv.w;
        q[u] = m[u].x*m[u].x + m[u].y*m[u].y + m[u].z*m[u].z + m[u].w*m[u].w;
    }
    #pragma unroll
    for (int u = 0; u < 4; u++) {
        d[u] += __shfl_xor_sync(FULLM, d[u], 1);
        q[u] += __shfl_xor_sync(FULLM, q[u], 1);
    }
    float a0 = (lane & 1) ? q[0] : d[0];
    float a1 = (lane & 1) ? q[1] : d[1];
    float a2 = (lane & 1) ? q[2] : d[2];
    float a3 = (lane & 1) ? q[3] : d[3];
    a0 += __shfl_xor_sync(FULLM, a0, 2);
    a1 += __shfl_xor_sync(FULLM, a1, 2);
    a2 += __shfl_xor_sync(FULLM, a2, 2);
    a3 += __shfl_xor_sync(FULLM, a3, 2);
    float b0 = (lane & 2) ? a2 : a0;
    float b1 = (lane & 2) ? a3 : a1;
    b0 += __shfl_xor_sync(FULLM, b0, 4);
    b1 += __shfl_xor_sync(FULLM, b1, 4);
    float cc = (lane & 4) ? b1 : b0;
    cc += __shfl_xor_sync(FULLM, cc, 8);
    cc += __shfl_xor_sync(FULLM, cc, 16);
    const float qq = __shfl_xor_sync(FULLM, cc, 1);   // q of same row onto d-lanes
    if (lane < 8 && !(lane & 1)) {
        const int row = ((lane & 2) ? 2 : 0) + ((lane & 4) ? 1 : 0);
        if (row >= minrow) {
            const float e = __expf(ks * (cc * ikn * rsqrtf(fmaxf(qq, 1e-16f))) - stab);
            ring[(lr0 + row + 3) & 15] = e;
        }
    }
}

__global__ void __launch_bounds__(TPB, 2) k_all(
    const float* __restrict__ x, const float* __restrict__ W,
    const float* __restrict__ bvec, const float* __restrict__ mem,
    float* __restrict__ out)
{
    __shared__ __align__(16) float sF[144];
    __shared__ float sP[12];                  // 0:ks 1:stab 2:ikn 3:sharp 4..10:shift
    __shared__ float sRing[NWARPS][16];       // warp-private e rings
    __shared__ float sRed[NWARPS * DIM];
    __shared__ float sZw[NWARPS];
    __shared__ int   sLast;

    const int tid = threadIdx.x, warp = tid >> 5, lane = tid & 31;
    const int bid = blockIdx.x;

    // ---------------- stage 1: factor partials (blocks 0..FB-1) ----------------
    if (bid < FB) {
        const int kb = bid / 5, fb = bid % 5;
        const int f = fb * 32 + lane;
        float a = 0.f;
        if (f < NF) {
            const int k0 = kb * 32 + warp * 4;
            #pragma unroll
            for (int i = 0; i < 4; i++)
                a += __ldg(&x[k0 + i]) * __ldg(&W[(size_t)(k0 + i) * NF + f]);
        }
        sRed[warp * 32 + lane] = a;
        __syncthreads();
        if (warp == 0) {
            float s = a;
            #pragma unroll
            for (int w = 1; w < NWARPS; w++) s += sRed[w * 32 + lane];
            g_fpart[kb][fb * 32 + lane] = s;
        }
        __threadfence();
        __syncthreads();
        if (tid == 0) atomicAdd(&g_cnt1, 1);
    }

    // ---------------- grid sync on factor partials ----------------
    if (tid == 0) {
        int v;
        do {
            asm volatile("ld.global.acquire.gpu.b32 %0, [%1];" : "=r"(v) : "l"(&g_cnt1));
            if (v < FB) __nanosleep(128);
        } while (v < FB);
    }
    __syncthreads();

    // ---------------- per-block prep (L2-hot partials) ----------------
    if (tid < 160) {
        float s = 0.f;
        #pragma unroll 8
        for (int p = 0; p < KCH; p++) s += g_fpart[p][tid];
        if (tid < 144) sF[tid] = (tid < NF) ? s + __ldg(&bvec[tid]) : 0.f;
    }
    __syncthreads();
    if (warp < 4) {
        const float v = sF[warp * 32 + lane];
        float sq = fullred(v * v);
        if (lane == 0) sZw[warp] = sq;
    }
    __syncthreads();
    if (tid == 0) {
        const float tot = sZw[0] + sZw[1] + sZw[2] + sZw[3];
        const float ks = sF[DIM];
        sP[0] = ks;
        sP[1] = fabsf(ks);                     // stabilizer (constant cancels in normalization)
        sP[2] = 1.f / fmaxf(sqrtf(tot), 1e-8f);
        sP[3] = fmaxf(sF[NF - 1], 0.f) + 1.f;  // sharpening
        float mx = -1e30f;
        #pragma unroll
        for (int j = 0; j < 7; j++) mx = fmaxf(mx, sF[DIM + 2 + j]);
        float ssum = 0.f, ev[7];
        #pragma unroll
        for (int j = 0; j < 7; j++) { ev[j] = expf(sF[DIM + 2 + j] - mx); ssum += ev[j]; }
        #pragma unroll
        for (int j = 0; j < 7; j++) sP[4 + j] = ev[j] / ssum;
        // gate = softmax(single element) == 1.0 exactly -> previous_weighting unused
    }
    __syncthreads();

    // ---------------- warp-private streaming (NO block barrier in loop) ----------------
    const float4 kv = ((const float4*)sF)[lane];
    const float ks = sP[0], stab = sP[1], ikn = sP[2], sharp = sP[3];
    float* ring = sRing[warp];

    const int gw = bid * NWARPS + warp;
    const int gs = (int)(((long long)gw * NG) / NWT);
    const int ge = (int)(((long long)(gw + 1) * NG) / NWT);
    const int len = ge - gs;            // ~54 groups of 4 rows
    const int rs = gs * 4;

    float4 m0[4], m1[4], m2[4], m3[4];
    {   // prologue: left-halo e (rows rs-3..rs-1) + group 0 e; groups 0,1 resident
        float4 mP[4];
        loadgrp_wrap(mP, mem, rs - 4, lane);
        loadgrp_fast(m0, mem, rs,     lane);
        loadgrp_fast(m1, mem, rs + 4, lane);
        bfly_e(mP, kv, ks, stab, ikn, ring, -4, lane, 1);
        bfly_e(m0, kv, ks, stab, ikn, ring,  0, lane, 0);
    }

    float4 acc = make_float4(0.f, 0.f, 0.f, 0.f);
    float zacc = 0.f;
    float pwprev = 0.f;

#define ACCG(MP) do {                                                          \
        _Pragma("unroll")                                                      \
        for (int r = 0; r < 4; r++) {                                          \
            const float pwb = __shfl_sync(FULLM, pwprev, r);                   \
            acc.x += pwb * MP[r].x; acc.y += pwb * MP[r].y;                    \
            acc.z += pwb * MP[r].z; acc.w += pwb * MP[r].w;                    \
        }                                                                      \
    } while (0)

    // step G: load(G+2) -> bfly(G+1) -> acc(G-1, pwprev) -> syncwarp -> pw(G)
#define STEP(MPRV, MNXT, MLD, G) do {                                          \
        if ((G) + 2 <= len) {                                                  \
            const int rb = rs + ((G) + 2) * 4;                                 \
            if (rb + 4 <= N_SLOTS) loadgrp_fast(MLD, mem, rb, lane);           \
            else                   loadgrp_wrap(MLD, mem, rb, lane);           \
        }                                                                      \
        bfly_e(MNXT, kv, ks, stab, ikn, ring, ((G) + 1) * 4, lane, 0);         \
        if ((G) >= 1) ACCG(MPRV);                                              \
        __syncwarp();                                                          \
        pwprev = 0.f;                                                          \
        if (lane < 4) {                                                        \
            const int lr = (G) * 4 + lane;                                     \
            float tc = 0.f;                                                    \
            _Pragma("unroll")                                                  \
            for (int j = 0; j < 7; j++) tc += sP[4 + j] * ring[(lr + j) & 15]; \
            pwprev = __powf(tc, sharp);   /* tc > 0 always */                  \
            zacc += pwprev;                                                    \
        }                                                                      \
    } while (0)

    int g = 0;
    while (g < len) {
        STEP(m3, m1, m2, g); g++; if (g >= len) break;
        STEP(m0, m2, m3, g); g++; if (g >= len) break;
        STEP(m1, m3, m0, g); g++; if (g >= len) break;
        STEP(m2, m0, m1, g); g++;
    }
    // epilogue: acc for the final group (len-1)
    switch ((len - 1) & 3) {
        case 0: ACCG(m0); break;
        case 1: ACCG(m1); break;
        case 2: ACCG(m2); break;
        default: ACCG(m3); break;
    }
#undef STEP
#undef ACCG

    // ---------------- deterministic block reduction + transposed store ----------------
    __syncthreads();
    ((float4*)(sRed + warp * DIM))[lane] = acc;
    zacc = fullred(zacc);
    if (lane == 0) sZw[warp] = zacc;
    __syncthreads();
    if (tid < DIM) {
        float u = 0.f;
        #pragma unroll
        for (int w = 0; w < NWARPS; w++) u += sRed[w * DIM + tid];
        g_UpartT[tid][bid] = u;
    }
    if (tid == 0) {
        float z = 0.f;
        #pragma unroll
        for (int w = 0; w < NWARPS; w++) z += sZw[w];
        g_Zpart[bid] = z;
    }
    __threadfence();
    __syncthreads();

    // ---------------- fused finisher: last-done block reduces in FIXED order ----------------
    if (tid == 0) sLast = (atomicAdd(&g_cnt2, 1) == MB - 1) ? 1 : 0;
    __syncthreads();
    if (sLast) {
        __threadfence();
        float z = 0.f;
        for (int i = lane; i < MB; i += 32) z += g_Zpart[i];
        z = fullred(z);
        for (int d = warp; d < DIM; d += NWARPS) {
            float u = 0.f;
            for (int i = lane; i < MB; i += 32) u += g_UpartT[d][i];
            u = fullred(u);
            if (lane == 0) out[d] = u / z;
        }
        if (tid == 0) { g_cnt1 = 0; g_cnt2 = 0; __threadfence(); }  // reset for next replay
    }
}

extern "C" void kernel_launch(void* const* d_in, const int* in_sizes, int n_in,
                              void* d_out, int out_size) {
    // Bind inputs by UNIQUE element count (robust to metadata ordering):
    // x=1024, prev=524288 (unused: gate==1), mem=67108864, W=141312, b=138
    const float *x = 0, *mem = 0, *W = 0, *b = 0;
    for (int i = 0; i < n_in; i++) {
        switch (in_sizes[i]) {
            case DIN:            x   = (const float*)d_in[i]; break;
            case N_SLOTS * DIM:  mem = (const float*)d_in[i]; break;
            case DIN * NF:       W   = (const float*)d_in[i]; break;
            case NF:             b   = (const float*)d_in[i]; break;
            default: break;      // previous_weighting (N_SLOTS): unused
        }
    }
    float* out = (float*)d_out;

    k_all<<<MB, TPB>>>(x, W, b, mem, out);
}